// round 3
// baseline (speedup 1.0000x reference)
#include <cuda_runtime.h>
#include <string.h>

// Problem constants (B, D, H, W, K) = (32, 256, 64, 64, 64)
constexpr int Bn  = 32;
constexpr int Dd  = 256;
constexpr int Nn  = 4096;     // H*W
constexpr int Kk  = 64;
constexpr int NC  = 64;       // n-rows per chunk
constexpr int CH  = 8;        // chunks per CTA
constexpr int NCH = Nn / (NC * CH);   // 8 CTAs along n per batch
constexpr int NTH = 256;

// smem layout (float words)
constexpr int XS_W = NC * Dd;        // 16384 swizzled X tile [n][d]
constexpr int CS_W = Kk * Dd;        // 16384 swizzled normalized codewords [k][d]
constexpr int PS_W = NC * Kk;        // 4096  raw logits P[n][k]
constexpr int A2_W = NC * Kk * 2;    // 8192  duplicated softmax A as float2 {a,a}
constexpr int SMEM_WORDS = XS_W + CS_W + PS_W + A2_W;     // 45056
constexpr int SMEM_BYTES = SMEM_WORDS * 4;                // 180224

typedef unsigned long long ull;

__device__ float g_Cn[Kk * Dd];                    // normalized codewords (k-major)
__device__ float g_S [Bn * Kk];                    // sum_n A[b,n,k]
__device__ float g_part[(size_t)Bn * NCH * Kk * Dd];  // 16 MB partial E

#define FMA2(acc, a, b) asm("fma.rn.f32x2 %0, %1, %2, %0;" : "+l"(acc) : "l"(a), "l"(b))

static __device__ __forceinline__ float2 unpack2(ull v) {
    float2 f;
    asm("mov.b64 {%0,%1}, %2;" : "=f"(f.x), "=f"(f.y) : "l"(v));
    return f;
}

// ---------------- prep: normalize codewords, zero g_S ----------------
__global__ void prep_kernel(const float* __restrict__ C) {
    int t = blockIdx.x * blockDim.x + threadIdx.x;   // 0..2047
    if (t < Bn * Kk) g_S[t] = 0.f;
    int k = t >> 5;            // one warp per codeword, k in [0,64)
    int l = t & 31;
    const float* row = C + k * Dd;
    float v[8];
    float ss = 0.f;
#pragma unroll
    for (int j = 0; j < 8; j++) { v[j] = row[l + 32 * j]; ss += v[j] * v[j]; }
#pragma unroll
    for (int o = 16; o > 0; o >>= 1) ss += __shfl_xor_sync(0xffffffffu, ss, o);
    float rs = 1.f / fmaxf(sqrtf(ss), 1e-8f);
#pragma unroll
    for (int j = 0; j < 8; j++) g_Cn[k * Dd + l + 32 * j] = v[j] * rs;
}

// ---------------- main fused kernel ----------------
__global__ __launch_bounds__(NTH, 1) void main_kernel(const float* __restrict__ X) {
    extern __shared__ float sm[];
    float* Xs  = sm;                       // swizzled: word n*256 + (d ^ 2*(n&15))
    float* Cs  = Xs + XS_W;                // swizzled: word k*256 + (d ^ 2*((k>>2)&15))
    float* Ps  = Cs + CS_W;                // P[n][k]
    float* A2s = Ps + PS_W;                // float2 dup A at f2-index n*64 + k

    const int b = blockIdx.y;
    const int g = blockIdx.x;
    const int t = threadIdx.x;
    const int w = t >> 5;
    const int l = t & 31;

    // load normalized codewords into swizzled smem
    for (int i = t; i < Kk * Dd; i += NTH) {
        int k = i >> 8, d = i & 255;
        Cs[k * 256 + (d ^ (2 * ((k >> 2) & 15)))] = g_Cn[i];
    }

    ull Eacc[8][4];                        // [kk][jj] packed float2 over d pairs
#pragma unroll
    for (int kk = 0; kk < 8; kk++)
#pragma unroll
        for (int jj = 0; jj < 4; jj++) Eacc[kk][jj] = 0ull;

    float sA0 = 0.f, sA1 = 0.f;
    const float* Xb = X + (size_t)b * Dd * Nn;

    for (int c = 0; c < CH; c++) {
        const int n0 = (g * CH + c) * NC;
        __syncthreads();
        // ---- transpose-load X chunk: Xs[n][d] = X[b][d][n0+n] ----
#pragma unroll 4
        for (int i = 0; i < 64; i++) {
            int idx = i * NTH + t;
            int d = idx >> 6, n = idx & 63;
            Xs[n * 256 + (d ^ (2 * (n & 15)))] = Xb[(size_t)d * Nn + n0 + n];
        }
        __syncthreads();

        // ---- row norms: warp w owns rows w*8 .. w*8+7 ----
        float rno[8];
        const float2* X2c = (const float2*)Xs;
#pragma unroll
        for (int r = 0; r < 8; r++) {
            int n = w * 8 + r;
            int sx = n & 15;
            float ss = 0.f;
#pragma unroll
            for (int jj = 0; jj < 4; jj++) {
                float2 v = X2c[n * 128 + ((l ^ sx) + 32 * jj)];
                ss += v.x * v.x + v.y * v.y;
            }
#pragma unroll
            for (int o = 16; o > 0; o >>= 1) ss += __shfl_xor_sync(0xffffffffu, ss, o);
            rno[r] = 1.f / fmaxf(sqrtf(ss), 1e-8f);
        }

        // ---- L matmul: P[n][k] = sum_d Xf[n][d] * Cn[k][d] (f32x2 over d) ----
        {
            const int n0t = (t >> 4) * 4;
            const int k0t = (t & 15) * 4;
            ull acc[4][4];
#pragma unroll
            for (int i = 0; i < 4; i++)
#pragma unroll
                for (int j = 0; j < 4; j++) acc[i][j] = 0ull;

            const ull* Xu = (const ull*)Xs;
            const ull* Cu = (const ull*)Cs;
#pragma unroll 2
            for (int dp = 0; dp < 128; dp++) {
                ull xv[4], cv[4];
#pragma unroll
                for (int i = 0; i < 4; i++) {
                    int n = n0t + i;
                    xv[i] = Xu[n * 128 + (dp ^ (n & 15))];
                }
#pragma unroll
                for (int j = 0; j < 4; j++) {
                    int k = k0t + j;
                    cv[j] = Cu[k * 128 + (dp ^ ((k >> 2) & 15))];
                }
#pragma unroll
                for (int i = 0; i < 4; i++)
#pragma unroll
                    for (int j = 0; j < 4; j++) FMA2(acc[i][j], xv[i], cv[j]);
            }
#pragma unroll
            for (int i = 0; i < 4; i++)
#pragma unroll
                for (int j = 0; j < 4; j++) {
                    float2 f = unpack2(acc[i][j]);
                    Ps[(n0t + i) * 64 + k0t + j] = f.x + f.y;
                }
        }
        __syncthreads();

        // ---- softmax over k (warp-row, temperature = 1/||x||) ----
#pragma unroll
        for (int r = 0; r < 8; r++) {
            int n = w * 8 + r;
            float p0 = Ps[n * 64 + l]      * rno[r];
            float p1 = Ps[n * 64 + l + 32] * rno[r];
            float m = fmaxf(p0, p1);
#pragma unroll
            for (int o = 16; o > 0; o >>= 1) m = fmaxf(m, __shfl_xor_sync(0xffffffffu, m, o));
            float e0 = __expf(p0 - m);
            float e1 = __expf(p1 - m);
            float s = e0 + e1;
#pragma unroll
            for (int o = 16; o > 0; o >>= 1) s += __shfl_xor_sync(0xffffffffu, s, o);
            float inv = 1.f / s;
            float a0 = e0 * inv, a1 = e1 * inv;
            sA0 += a0; sA1 += a1;
            float2* A2 = (float2*)A2s;
            A2[n * 64 + l]      = make_float2(a0, a0);
            A2[n * 64 + l + 32] = make_float2(a1, a1);
        }
        __syncthreads();

        // ---- aggregate: E[k][d] += sum_n A[n][k] * Xf[n][d] ----
        {
            const ull* Xu = (const ull*)Xs;
            const ulonglong2* A16 = (const ulonglong2*)A2s;
#pragma unroll 2
            for (int n = 0; n < NC; n++) {
                int sx = n & 15;
                ull xv[4];
#pragma unroll
                for (int jj = 0; jj < 4; jj++)
                    xv[jj] = Xu[n * 128 + ((l ^ sx) + 32 * jj)];
                ull av[8];
#pragma unroll
                for (int q = 0; q < 4; q++) {
                    ulonglong2 p = A16[n * 32 + w * 4 + q];
                    av[2 * q]     = p.x;
                    av[2 * q + 1] = p.y;
                }
#pragma unroll
                for (int kk = 0; kk < 8; kk++)
#pragma unroll
                    for (int jj = 0; jj < 4; jj++) FMA2(Eacc[kk][jj], av[kk], xv[jj]);
            }
        }
    }

    // ---- flush partial E to scratch (no atomics) ----
    float2* P2 = (float2*)(g_part + ((size_t)(b * NCH + g)) * Kk * Dd);
#pragma unroll
    for (int kk = 0; kk < 8; kk++) {
        int k = w * 8 + kk;
#pragma unroll
        for (int jj = 0; jj < 4; jj++) {
            int d = 2 * l + 64 * jj;
            P2[(k * Dd + d) >> 1] = unpack2(Eacc[kk][jj]);
        }
    }
    atomicAdd(&g_S[b * Kk + l],      sA0);
    atomicAdd(&g_S[b * Kk + l + 32], sA1);
}

// ---------------- finalize: reduce partials, subtract S*C ----------------
__global__ void fin_kernel(const float* __restrict__ Craw, float* __restrict__ out) {
    int i = blockIdx.x * blockDim.x + threadIdx.x;   // float4 index, 131072 total
    int idx = i * 4;
    int b = idx >> 14;              // / (K*D)
    int r = idx & 16383;
    int k = r >> 8;
    const float4* Pp = (const float4*)g_part;
    int stride4 = (Kk * Dd) >> 2;
    int base = b * NCH * stride4 + (r >> 2);
    float4 s = make_float4(0.f, 0.f, 0.f, 0.f);
#pragma unroll
    for (int g = 0; g < NCH; g++) {
        float4 p = Pp[base + g * stride4];
        s.x += p.x; s.y += p.y; s.z += p.z; s.w += p.w;
    }
    float Sv = g_S[b * Kk + k];
    float4 c = ((const float4*)Craw)[r >> 2];
    s.x -= Sv * c.x; s.y -= Sv * c.y; s.z -= Sv * c.z; s.w -= Sv * c.w;
    ((float4*)out)[i] = s;
}

extern "C" void kernel_launch(void* const* d_in, const int* in_sizes, int n_in,
                              void* d_out, int out_size) {
    const float* X = (const float*)d_in[0];
    const float* C = (const float*)d_in[1];
    float* out = (float*)d_out;

    cudaFuncSetAttribute(main_kernel, cudaFuncAttributeMaxDynamicSharedMemorySize, SMEM_BYTES);

    prep_kernel<<<2, 1024>>>(C);
    main_kernel<<<dim3(NCH, Bn), NTH, SMEM_BYTES>>>(X);
    fin_kernel<<<(Bn * Kk * Dd / 4 + 255) / 256, 256>>>(C, out);
}